// round 13
// baseline (speedup 1.0000x reference)
#include <cuda_runtime.h>
#include <math.h>
#include <float.h>
#include <stdint.h>

// Problem constants
#define Bn   4
#define Dd   256
#define Nn   2048
#define Mm   2048
#define Hh   4
#define DIMh 64

// Scratch (allocation-free: __device__ globals)
__device__ float g_q[Bn * Dd * Nn];
__device__ float g_k[Bn * Dd * Mm];
__device__ float g_v[Bn * Dd * Mm];
__device__ float g_msg[Bn * Dd * Nn];
__device__ float g_message[Bn * Dd * Nn];
__device__ float g_h[Bn * 2 * Dd * Nn];
// P_unnorm planes, packed bf16x2 along m (hi/lo split)
__device__ uint32_t g_ph[(size_t)Bn * Hh * Nn * Mm / 2];   // 134 MB
__device__ uint32_t g_pl[(size_t)Bn * Hh * Nn * Mm / 2];   // 134 MB
__device__ float g_psum[(size_t)Bn * Hh * Nn * 32];        // per-(row, m-tile) partials
__device__ float g_rowsum[Bn * Hh * Nn];

// ---------------------------------------------------------------------------
// bf16 split helpers
// ---------------------------------------------------------------------------
__device__ __forceinline__ void pack_split(float f0, float f1, uint32_t& h, uint32_t& l)
{
    uint32_t hp;
    asm("cvt.rn.bf16x2.f32 %0, %1, %2;" : "=r"(hp) : "f"(f1), "f"(f0));
    float r0 = f0 - __uint_as_float(hp << 16);
    float r1 = f1 - __uint_as_float(hp & 0xffff0000u);
    uint32_t lp;
    asm("cvt.rn.bf16x2.f32 %0, %1, %2;" : "=r"(lp) : "f"(r1), "f"(r0));
    h = hp; l = lp;
}

__device__ __forceinline__ void mma_bf16(float (&d)[4],
                                         uint32_t a0, uint32_t a1, uint32_t a2, uint32_t a3,
                                         uint32_t b0, uint32_t b1)
{
    asm volatile(
        "mma.sync.aligned.m16n8k16.row.col.f32.bf16.bf16.f32 "
        "{%0,%1,%2,%3}, {%4,%5,%6,%7}, {%8,%9}, {%0,%1,%2,%3};\n"
        : "+f"(d[0]), "+f"(d[1]), "+f"(d[2]), "+f"(d[3])
        : "r"(a0), "r"(a1), "r"(a2), "r"(a3), "r"(b0), "r"(b1));
}

__device__ __forceinline__ void mma3(float (&d)[4],
                                     const uint32_t (&ah)[4], const uint32_t (&al)[4],
                                     const uint32_t (&bh)[2], const uint32_t (&bl)[2])
{
    mma_bf16(d, al[0], al[1], al[2], al[3], bh[0], bh[1]);
    mma_bf16(d, ah[0], ah[1], ah[2], ah[3], bl[0], bl[1]);
    mma_bf16(d, ah[0], ah[1], ah[2], ah[3], bh[0], bh[1]);
}

// ldmatrix: 4 8x8 b16 matrices -> 4 regs
__device__ __forceinline__ void ldsm_x4(uint32_t (&r)[4], uint32_t saddr)
{
    asm volatile("ldmatrix.sync.aligned.m8n8.x4.shared.b16 {%0,%1,%2,%3}, [%4];"
                 : "=r"(r[0]), "=r"(r[1]), "=r"(r[2]), "=r"(r[3]) : "r"(saddr));
}

__device__ __forceinline__ uint32_t cvta_smem(const void* p)
{
    return (uint32_t)__cvta_generic_to_shared(p);
}

#define GST 20   // GEMM/PV tile stride (16 u32 + 4 pad); 20r%32 phases conflict-free
#define AST 36   // scores tile stride (32 u32 + 4 pad); 36r%32 phases conflict-free

// ---------------------------------------------------------------------------
// 1x1-conv GEMM (bf16 3-term): Y[b,o,n] = sum_c W[o,c]*X[b,c,n] + bias[o]
// Block 64(o) x 128(n), K-chunk 32 channels, 8 warps (2x4), warp tile 32x32.
// Fragment loads via ldmatrix.x4.
// ---------------------------------------------------------------------------
template<int OUTC, int INC, bool CONCAT, bool BNRELU>
__global__ void __launch_bounds__(256)
gemm_mma(const float* __restrict__ W, const float* __restrict__ bias,
         const float* __restrict__ X0, const float* __restrict__ X1,
         float* __restrict__ Y,
         const float* __restrict__ gamma, const float* __restrict__ beta,
         const float* __restrict__ rmean, const float* __restrict__ rvar)
{
    __shared__ uint32_t AsH[64][GST],  AsL[64][GST];    // [o][c-pair]
    __shared__ uint32_t BsH[128][GST], BsL[128][GST];   // [n][c-pair]

    const int tid = threadIdx.x;
    const int n0 = blockIdx.x * 128;
    const int o0 = blockIdx.y * 64;
    const int b  = blockIdx.z;
    const int XC = CONCAT ? (INC / 2) : INC;
    const float* x0 = X0 + (size_t)b * XC * Nn;
    const float* x1 = CONCAT ? (X1 + (size_t)b * XC * Nn) : nullptr;

    const int w      = tid >> 5;
    const int lane   = tid & 31;
    const int g      = lane >> 2;
    const int tg     = lane & 3;
    const int warp_m = w >> 2;
    const int warp_n = w & 3;

    float acc[2][4][4] = {};

    const int o_ld  = tid >> 2;
    const int q4    = tid & 3;
    const int cp_ld = tid >> 4;
    const int nb_ld = tid & 15;

    const uint32_t aHb = cvta_smem(AsH), aLb = cvta_smem(AsL);
    const uint32_t bHb = cvta_smem(BsH), bLb = cvta_smem(BsL);
    // ldmatrix lane offsets (u32 units)
    const int la = (lane & 15) * GST + ((lane >> 4) << 2);
    const int lb = ((lane & 7) + ((lane >> 4) << 3)) * GST + (((lane >> 3) & 1) << 2);

    for (int c0 = 0; c0 < INC; c0 += 32) {
        // --- W tile ---
        {
            const float* wp = W + (size_t)(o0 + o_ld) * INC + c0 + q4 * 8;
            float4 u = *(const float4*)(wp);
            float4 v = *(const float4*)(wp + 4);
            uint4 hh, ll;
            pack_split(u.x, u.y, hh.x, ll.x);
            pack_split(u.z, u.w, hh.y, ll.y);
            pack_split(v.x, v.y, hh.z, ll.z);
            pack_split(v.z, v.w, hh.w, ll.w);
            *(uint4*)&AsH[o_ld][q4 * 4] = hh;
            *(uint4*)&AsL[o_ld][q4 * 4] = ll;
        }
        // --- X tile ---
        {
            int c = c0 + 2 * cp_ld;
            const float *xr0, *xr1;
            if (!CONCAT || c < INC / 2) {
                xr0 = x0 + (size_t)c * Nn;
                xr1 = x0 + (size_t)(c + 1) * Nn;
            } else {
                xr0 = x1 + (size_t)(c - INC / 2) * Nn;
                xr1 = x1 + (size_t)(c + 1 - INC / 2) * Nn;
            }
            #pragma unroll
            for (int i = 0; i < 8; i++) {
                int n = nb_ld + 16 * i;
                pack_split(xr0[n0 + n], xr1[n0 + n], BsH[n][cp_ld], BsL[n][cp_ld]);
            }
        }
        __syncthreads();

        #pragma unroll
        for (int st = 0; st < 2; st++) {
            const int kc = st * 8;
            uint32_t ah[2][4], al[2][4], bh[4][2], bl[4][2];
            #pragma unroll
            for (int mt = 0; mt < 2; mt++) {
                int idx = (warp_m * 32 + mt * 16) * GST + la + kc;
                ldsm_x4(ah[mt], aHb + idx * 4);
                ldsm_x4(al[mt], aLb + idx * 4);
            }
            #pragma unroll
            for (int pr = 0; pr < 2; pr++) {
                int idx = (warp_n * 32 + pr * 16) * GST + lb + kc;
                uint32_t th[4], tl[4];
                ldsm_x4(th, bHb + idx * 4);
                ldsm_x4(tl, bLb + idx * 4);
                bh[pr*2  ][0] = th[0]; bh[pr*2  ][1] = th[1];
                bh[pr*2+1][0] = th[2]; bh[pr*2+1][1] = th[3];
                bl[pr*2  ][0] = tl[0]; bl[pr*2  ][1] = tl[1];
                bl[pr*2+1][0] = tl[2]; bl[pr*2+1][1] = tl[3];
            }
            #pragma unroll
            for (int mt = 0; mt < 2; mt++)
                #pragma unroll
                for (int nt = 0; nt < 4; nt++)
                    mma3(acc[mt][nt], ah[mt], al[mt], bh[nt], bl[nt]);
        }
        __syncthreads();
    }

    float* yb = Y + (size_t)b * OUTC * Nn;
    #pragma unroll
    for (int mt = 0; mt < 2; mt++) {
        int r0 = o0 + warp_m * 32 + mt * 16 + g;
        int r1 = r0 + 8;
        float bv0 = bias[r0], bv1 = bias[r1];
        float sc0 = 1.f, sh0 = 0.f, sc1 = 1.f, sh1 = 0.f;
        if (BNRELU) {
            float rs0 = rsqrtf(rvar[r0] + 1e-3f);
            sc0 = gamma[r0] * rs0; sh0 = beta[r0] - rmean[r0] * sc0;
            float rs1 = rsqrtf(rvar[r1] + 1e-3f);
            sc1 = gamma[r1] * rs1; sh1 = beta[r1] - rmean[r1] * sc1;
        }
        #pragma unroll
        for (int nt = 0; nt < 4; nt++) {
            int n = n0 + warp_n * 32 + nt * 8 + 2 * tg;
            float t0 = acc[mt][nt][0] + bv0;
            float t1 = acc[mt][nt][1] + bv0;
            float t2 = acc[mt][nt][2] + bv1;
            float t3 = acc[mt][nt][3] + bv1;
            if (BNRELU) {
                t0 = fmaxf(t0 * sc0 + sh0, 0.f);
                t1 = fmaxf(t1 * sc0 + sh0, 0.f);
                t2 = fmaxf(t2 * sc1 + sh1, 0.f);
                t3 = fmaxf(t3 * sc1 + sh1, 0.f);
            }
            *(float2*)&yb[(size_t)r0 * Nn + n] = make_float2(t0, t1);
            *(float2*)&yb[(size_t)r1 * Nn + n] = make_float2(t2, t3);
        }
    }
}

// ---------------------------------------------------------------------------
// Scores + mask + exp: P_unnorm[bh,n,m] = mask ? exp(q·k/8) : 0, packed bf16
// hi/lo, plus per-(row, m-tile) partial sums. Block 128(n) x 64(m).
// Warps 2(n) x 4(m); warp tile 64n x 16m. Fragment loads via ldmatrix.
// ---------------------------------------------------------------------------
__global__ void __launch_bounds__(256)
attn_scores_p(const float* __restrict__ mask)
{
    extern __shared__ uint32_t sm[];
    uint32_t* QH = sm;                                  // [128][AST]
    uint32_t* QL = sm + 128 * AST;
    uint32_t* KH = sm + 2 * 128 * AST;                  // [64][AST]
    uint32_t* KL = sm + 2 * 128 * AST + 64 * AST;
    float* RED   = (float*)(sm + 2 * 128 * AST + 2 * 64 * AST);  // [4][128]

    const int tid = threadIdx.x;
    const int m0 = blockIdx.x * 64;
    const int n0 = blockIdx.y * 128;
    const int bh = blockIdx.z;
    const int b = bh >> 2, h = bh & 3;
    const float* qg = g_q + (size_t)b * Dd * Nn;
    const float* kg = g_k + (size_t)b * Dd * Mm;

    const int w      = tid >> 5;
    const int lane   = tid & 31;
    const int g      = lane >> 2;
    const int tg     = lane & 3;
    const int warp_m = w >> 2;   // n half
    const int warp_n = w & 3;    // m quarter (16 m)

    float acc[4][2][4] = {};

    const int dpg = tid >> 4;   // 0..15
    const int cbl = tid & 15;

    #pragma unroll
    for (int hf = 0; hf < 2; hf++) {
        int dp  = dpg + 16 * hf;           // d-pair 0..31
        int ch0 = (2 * dp) * Hh + h;
        const float* q0 = qg + (size_t)ch0 * Nn + n0;
        const float* q1 = qg + (size_t)(ch0 + Hh) * Nn + n0;
        const float* k0 = kg + (size_t)ch0 * Mm + m0;
        const float* k1 = kg + (size_t)(ch0 + Hh) * Mm + m0;
        #pragma unroll
        for (int i = 0; i < 8; i++) {
            int n = cbl + 16 * i;
            pack_split(q0[n], q1[n], QH[n * AST + dp], QL[n * AST + dp]);
        }
        #pragma unroll
        for (int i = 0; i < 4; i++) {
            int m = cbl + 16 * i;
            pack_split(k0[m], k1[m], KH[m * AST + dp], KL[m * AST + dp]);
        }
    }
    __syncthreads();

    const uint32_t qHb = cvta_smem(QH), qLb = cvta_smem(QL);
    const uint32_t kHb = cvta_smem(KH), kLb = cvta_smem(KL);
    const int la = (lane & 15) * AST + ((lane >> 4) << 2);
    const int lb = ((lane & 7) + ((lane >> 4) << 3)) * AST + (((lane >> 3) & 1) << 2);

    #pragma unroll
    for (int st = 0; st < 4; st++) {
        const int kc = st * 8;
        uint32_t ah[4][4], al[4][4], bh2[2][2], bl2[2][2];
        #pragma unroll
        for (int mt = 0; mt < 4; mt++) {
            int idx = (warp_m * 64 + mt * 16) * AST + la + kc;
            ldsm_x4(ah[mt], qHb + idx * 4);
            ldsm_x4(al[mt], qLb + idx * 4);
        }
        {
            int idx = (warp_n * 16) * AST + lb + kc;
            uint32_t th[4], tl[4];
            ldsm_x4(th, kHb + idx * 4);
            ldsm_x4(tl, kLb + idx * 4);
            bh2[0][0] = th[0]; bh2[0][1] = th[1];
            bh2[1][0] = th[2]; bh2[1][1] = th[3];
            bl2[0][0] = tl[0]; bl2[0][1] = tl[1];
            bl2[1][0] = tl[2]; bl2[1][1] = tl[3];
        }
        #pragma unroll
        for (int mt = 0; mt < 4; mt++)
            #pragma unroll
            for (int nt = 0; nt < 2; nt++)
                mma3(acc[mt][nt], ah[mt], al[mt], bh2[nt], bl2[nt]);
    }

    // --- epilogue: mask, exp, pack-store P, partial row sums ---
    float rsum[4][2];
    #pragma unroll
    for (int mt = 0; mt < 4; mt++) { rsum[mt][0] = 0.f; rsum[mt][1] = 0.f; }

    #pragma unroll
    for (int mt = 0; mt < 4; mt++) {
        int nr0 = n0 + warp_m * 64 + mt * 16 + g;
        int nr1 = nr0 + 8;
        #pragma unroll
        for (int nt = 0; nt < 2; nt++) {
            int gm = m0 + warp_n * 16 + nt * 8 + 2 * tg;
            float2 mk0 = *(const float2*)&mask[((size_t)b * Nn + nr0) * Mm + gm];
            float2 mk1 = *(const float2*)&mask[((size_t)b * Nn + nr1) * Mm + gm];
            float p0 = (mk0.x > 0.f) ? __expf(acc[mt][nt][0] * 0.125f) : 0.f;
            float p1 = (mk0.y > 0.f) ? __expf(acc[mt][nt][1] * 0.125f) : 0.f;
            float p2 = (mk1.x > 0.f) ? __expf(acc[mt][nt][2] * 0.125f) : 0.f;
            float p3 = (mk1.y > 0.f) ? __expf(acc[mt][nt][3] * 0.125f) : 0.f;
            uint32_t hh, ll;
            size_t base0 = ((size_t)bh * Nn + nr0) * (Mm / 2) + (gm >> 1);
            size_t base1 = ((size_t)bh * Nn + nr1) * (Mm / 2) + (gm >> 1);
            pack_split(p0, p1, hh, ll); g_ph[base0] = hh; g_pl[base0] = ll;
            pack_split(p2, p3, hh, ll); g_ph[base1] = hh; g_pl[base1] = ll;
            rsum[mt][0] += p0 + p1;
            rsum[mt][1] += p2 + p3;
        }
    }
    #pragma unroll
    for (int mt = 0; mt < 4; mt++)
        #pragma unroll
        for (int r = 0; r < 2; r++) {
            rsum[mt][r] += __shfl_xor_sync(0xffffffffu, rsum[mt][r], 1);
            rsum[mt][r] += __shfl_xor_sync(0xffffffffu, rsum[mt][r], 2);
        }
    if (tg == 0) {
        #pragma unroll
        for (int mt = 0; mt < 4; mt++) {
            int rl = warp_m * 64 + mt * 16 + g;
            RED[warp_n * 128 + rl    ] = rsum[mt][0];
            RED[warp_n * 128 + rl + 8] = rsum[mt][1];
        }
    }
    __syncthreads();
    if (tid < 128) {
        float s = RED[tid] + RED[128 + tid] + RED[256 + tid] + RED[384 + tid];
        g_psum[((size_t)bh * Nn + n0 + tid) * 32 + blockIdx.x] = s;
    }
}

// ---------------------------------------------------------------------------
// Row-sum reduce: g_rowsum[row] = sum of 32 partials. 32768 rows.
// ---------------------------------------------------------------------------
__global__ void __launch_bounds__(256)
rowsum_reduce()
{
    int row = blockIdx.x * 256 + threadIdx.x;
    const float4* p = (const float4*)(g_psum + (size_t)row * 32);
    float s = 0.f;
    #pragma unroll
    for (int i = 0; i < 8; i++) {
        float4 v = p[i];
        s += v.x + v.y + v.z + v.w;
    }
    g_rowsum[row] = s;
}

// ---------------------------------------------------------------------------
// PV (bf16 3-term): msg[b,d*4+h,n] = (sum_m P_unnorm[bh,n,m]*v[..,m]) / rowsum[n]
// Block 64(d) x 128(n); m streamed in chunks of 32. Fragment loads via ldmatrix.
// ---------------------------------------------------------------------------
__global__ void __launch_bounds__(256)
attn_pv_mma()
{
    __shared__ uint32_t VHs[64][GST],  VLs[64][GST];    // [d][m-pair]
    __shared__ uint32_t PHs[128][GST], PLs[128][GST];   // [n][m-pair]

    const int tid = threadIdx.x;
    const int n0 = blockIdx.x * 128;
    const int bh = blockIdx.z;
    const int b = bh >> 2, h = bh & 3;
    const float* vg = g_v + (size_t)b * Dd * Mm;
    const uint32_t* PHg = g_ph + (size_t)bh * Nn * (Mm / 2);
    const uint32_t* PLg = g_pl + (size_t)bh * Nn * (Mm / 2);

    const int w      = tid >> 5;
    const int lane   = tid & 31;
    const int g      = lane >> 2;
    const int tg     = lane & 3;
    const int warp_m = w >> 2;   // d half
    const int warp_n = w & 3;

    float acc[2][4][4] = {};

    const int vd = tid >> 2;
    const int vq = tid & 3;
    const int pn = tid >> 1;
    const int ph = tid & 1;

    const uint32_t vHb = cvta_smem(VHs), vLb = cvta_smem(VLs);
    const uint32_t pHb = cvta_smem(PHs), pLb = cvta_smem(PLs);
    const int la = (lane & 15) * GST + ((lane >> 4) << 2);
    const int lb = ((lane & 7) + ((lane >> 4) << 3)) * GST + (((lane >> 3) & 1) << 2);

    for (int m0 = 0; m0 < Mm; m0 += 32) {
        // V tile
        {
            const float* vp = vg + (size_t)(vd * Hh + h) * Mm + m0 + vq * 8;
            float4 u = *(const float4*)(vp);
            float4 v4 = *(const float4*)(vp + 4);
            uint4 hh, ll;
            pack_split(u.x,  u.y,  hh.x, ll.x);
            pack_split(u.z,  u.w,  hh.y, ll.y);
            pack_split(v4.x, v4.y, hh.z, ll.z);
            pack_split(v4.z, v4.w, hh.w, ll.w);
            *(uint4*)&VHs[vd][vq * 4] = hh;
            *(uint4*)&VLs[vd][vq * 4] = ll;
        }
        // P tile: direct u32 loads
        {
            size_t base = (size_t)(n0 + pn) * (Mm / 2) + (m0 >> 1) + ph * 8;
            uint4 h0 = *(const uint4*)(PHg + base);
            uint4 h1 = *(const uint4*)(PHg + base + 4);
            uint4 l0 = *(const uint4*)(PLg + base);
            uint4 l1 = *(const uint4*)(PLg + base + 4);
            *(uint4*)&PHs[pn][ph * 8    ] = h0;
            *(uint4*)&PHs[pn][ph * 8 + 4] = h1;
            *(uint4*)&PLs[pn][ph * 8    ] = l0;
            *(uint4*)&PLs[pn][ph * 8 + 4] = l1;
        }
        __syncthreads();

        #pragma unroll
        for (int st = 0; st < 2; st++) {
            const int kc = st * 8;
            uint32_t ah[2][4], al[2][4], bh2[4][2], bl2[4][2];
            #pragma unroll
            for (int mt = 0; mt < 2; mt++) {
                int idx = (warp_m * 32 + mt * 16) * GST + la + kc;
                ldsm_x4(ah[mt], vHb + idx * 4);
                ldsm_x4(al[mt], vLb + idx * 4);
            }
            #pragma unroll
            for (int pr = 0; pr < 2; pr++) {
                int idx = (warp_n * 32 + pr * 16) * GST + lb + kc;
                uint32_t th[4], tl[4];
                ldsm_x4(th, pHb + idx * 4);
                ldsm_x4(tl, pLb + idx * 4);
                bh2[pr*2  ][0] = th[0]; bh2[pr*2  ][1] = th[1];
                bh2[pr*2+1][0] = th[2]; bh2[pr*2+1][1] = th[3];
                bl2[pr*2  ][0] = tl[0]; bl2[pr*2  ][1] = tl[1];
                bl2[pr*2+1][0] = tl[2]; bl2[pr*2+1][1] = tl[3];
            }
            #pragma unroll
            for (int mt = 0; mt < 2; mt++)
                #pragma unroll
                for (int nt = 0; nt < 4; nt++)
                    mma3(acc[mt][nt], ah[mt], al[mt], bh2[nt], bl2[nt]);
        }
        __syncthreads();
    }

    const float* rs = g_rowsum + (size_t)bh * Nn + n0;
    float* mp = g_msg + (size_t)b * Dd * Nn;
    #pragma unroll
    for (int mt = 0; mt < 2; mt++) {
        int d0 = warp_m * 32 + mt * 16 + g;
        int d1 = d0 + 8;
        #pragma unroll
        for (int nt = 0; nt < 4; nt++) {
            int n = warp_n * 32 + nt * 8 + 2 * tg;
            float inv0 = 1.f / rs[n];
            float inv1 = 1.f / rs[n + 1];
            *(float2*)&mp[(size_t)(d0 * Hh + h) * Nn + n0 + n] =
                make_float2(acc[mt][nt][0] * inv0, acc[mt][nt][1] * inv1);
            *(float2*)&mp[(size_t)(d1 * Hh + h) * Nn + n0 + n] =
                make_float2(acc[mt][nt][2] * inv0, acc[mt][nt][3] * inv1);
        }
    }
}

// ---------------------------------------------------------------------------
extern "C" void kernel_launch(void* const* d_in, const int* in_sizes, int n_in,
                              void* d_out, int out_size)
{
    const float* x      = (const float*)d_in[0];
    const float* source = (const float*)d_in[1];
    const float* mask   = (const float*)d_in[2];
    const float* Wq = (const float*)d_in[3];
    const float* bq = (const float*)d_in[4];
    const float* Wk = (const float*)d_in[5];
    const float* bk = (const float*)d_in[6];
    const float* Wv = (const float*)d_in[7];
    const float* bv = (const float*)d_in[8];
    const float* Wm = (const float*)d_in[9];
    const float* bm = (const float*)d_in[10];
    const float* W1 = (const float*)d_in[11];
    const float* b1 = (const float*)d_in[12];
    const float* gamma = (const float*)d_in[13];
    const float* beta  = (const float*)d_in[14];
    const float* rmean = (const float*)d_in[15];
    const float* rvar  = (const float*)d_in[16];
    const float* W2 = (const float*)d_in[17];
    const float* b2 = (const float*)d_in[18];
    float* out = (float*)d_out;

    float *qb, *kb, *vb, *msgb, *messageb, *hb;
    cudaGetSymbolAddress((void**)&qb, g_q);
    cudaGetSymbolAddress((void**)&kb, g_k);
    cudaGetSymbolAddress((void**)&vb, g_v);
    cudaGetSymbolAddress((void**)&msgb, g_msg);
    cudaGetSymbolAddress((void**)&messageb, g_message);
    cudaGetSymbolAddress((void**)&hb, g_h);

    const int SMEM_SCORES = (2 * 128 * AST + 2 * 64 * AST + 512) * 4;  // 57344 B
    cudaFuncSetAttribute(attn_scores_p,
                         cudaFuncAttributeMaxDynamicSharedMemorySize, SMEM_SCORES);

    // q, k, v projections
    gemm_mma<256, 256, false, false><<<dim3(16, 4, 4), 256>>>(
        Wq, bq, x, nullptr, qb, nullptr, nullptr, nullptr, nullptr);
    gemm_mma<256, 256, false, false><<<dim3(16, 4, 4), 256>>>(
        Wk, bk, source, nullptr, kb, nullptr, nullptr, nullptr, nullptr);
    gemm_mma<256, 256, false, false><<<dim3(16, 4, 4), 256>>>(
        Wv, bv, source, nullptr, vb, nullptr, nullptr, nullptr, nullptr);

    // attention: P_unnorm + partial sums, reduce, PV with normalization
    attn_scores_p<<<dim3(32, 16, 16), 256, SMEM_SCORES>>>(mask);
    rowsum_reduce<<<128, 256>>>();
    attn_pv_mma<<<dim3(16, 1, 16), 256>>>();

    // message projection
    gemm_mma<256, 256, false, false><<<dim3(16, 4, 4), 256>>>(
        Wm, bm, msgb, nullptr, messageb, nullptr, nullptr, nullptr, nullptr);

    // MLP layer 1 (concat[x, message]) + BN + ReLU
    gemm_mma<512, 512, true, true><<<dim3(16, 8, 4), 256>>>(
        W1, b1, x, messageb, hb, gamma, beta, rmean, rvar);

    // MLP layer 2 -> output
    gemm_mma<256, 512, false, false><<<dim3(16, 4, 4), 256>>>(
        W2, b2, hb, nullptr, out, nullptr, nullptr, nullptr, nullptr);
}

// round 14
// speedup vs baseline: 1.0374x; 1.0374x over previous
#include <cuda_runtime.h>
#include <math.h>
#include <float.h>
#include <stdint.h>

// Problem constants
#define Bn   4
#define Dd   256
#define Nn   2048
#define Mm   2048
#define Hh   4
#define DIMh 64

// Scratch (allocation-free: __device__ globals)
__device__ float g_q[Bn * Dd * Nn];
__device__ float g_k[Bn * Dd * Mm];
__device__ float g_v[Bn * Dd * Mm];
__device__ float g_msg[Bn * Dd * Nn];
__device__ float g_message[Bn * Dd * Nn];
__device__ float g_h[Bn * 2 * Dd * Nn];
// P_unnorm: interleaved (hi,lo) bf16x2 planes per m-pair
__device__ uint2 g_p[(size_t)Bn * Hh * Nn * Mm / 2];       // 268 MB
__device__ float g_psum[(size_t)Bn * Hh * Nn * 32];        // per-(row, m-tile) partials
__device__ float g_rowsum[Bn * Hh * Nn];
__device__ uint32_t g_maskbits[Bn * Nn * Mm / 32];         // 2 MB

// ---------------------------------------------------------------------------
// bf16 split helpers
// ---------------------------------------------------------------------------
__device__ __forceinline__ void pack_split(float f0, float f1, uint32_t& h, uint32_t& l)
{
    uint32_t hp;
    asm("cvt.rn.bf16x2.f32 %0, %1, %2;" : "=r"(hp) : "f"(f1), "f"(f0));
    float r0 = f0 - __uint_as_float(hp << 16);
    float r1 = f1 - __uint_as_float(hp & 0xffff0000u);
    uint32_t lp;
    asm("cvt.rn.bf16x2.f32 %0, %1, %2;" : "=r"(lp) : "f"(r1), "f"(r0));
    h = hp; l = lp;
}

__device__ __forceinline__ void mma_bf16(float (&d)[4],
                                         uint32_t a0, uint32_t a1, uint32_t a2, uint32_t a3,
                                         uint32_t b0, uint32_t b1)
{
    asm volatile(
        "mma.sync.aligned.m16n8k16.row.col.f32.bf16.bf16.f32 "
        "{%0,%1,%2,%3}, {%4,%5,%6,%7}, {%8,%9}, {%0,%1,%2,%3};\n"
        : "+f"(d[0]), "+f"(d[1]), "+f"(d[2]), "+f"(d[3])
        : "r"(a0), "r"(a1), "r"(a2), "r"(a3), "r"(b0), "r"(b1));
}

__device__ __forceinline__ void mma3(float (&d)[4],
                                     const uint32_t (&ah)[4], const uint32_t (&al)[4],
                                     const uint32_t (&bh)[2], const uint32_t (&bl)[2])
{
    mma_bf16(d, al[0], al[1], al[2], al[3], bh[0], bh[1]);
    mma_bf16(d, ah[0], ah[1], ah[2], ah[3], bl[0], bl[1]);
    mma_bf16(d, ah[0], ah[1], ah[2], ah[3], bh[0], bh[1]);
}

__device__ __forceinline__ void ldsm_x4(uint32_t (&r)[4], uint32_t saddr)
{
    asm volatile("ldmatrix.sync.aligned.m8n8.x4.shared.b16 {%0,%1,%2,%3}, [%4];"
                 : "=r"(r[0]), "=r"(r[1]), "=r"(r[2]), "=r"(r[3]) : "r"(saddr));
}

__device__ __forceinline__ uint32_t cvta_smem(const void* p)
{
    return (uint32_t)__cvta_generic_to_shared(p);
}

#define GST 20   // GEMM/PV tile stride (16 u32 + 4 pad)
#define AST 36   // scores tile stride (32 u32 + 4 pad)

// ---------------------------------------------------------------------------
// Mask bit-pack: one warp ballot per 32 elements.
// ---------------------------------------------------------------------------
__global__ void __launch_bounds__(256)
mask_pack(const float* __restrict__ mask)
{
    int idx = blockIdx.x * 256 + threadIdx.x;
    float v = mask[idx];
    unsigned bits = __ballot_sync(0xffffffffu, v > 0.f);
    if ((threadIdx.x & 31) == 0)
        g_maskbits[idx >> 5] = bits;
}

// ---------------------------------------------------------------------------
// 1x1-conv GEMM (bf16 3-term): Y[b,o,n] = sum_c W[o,c]*X[b,c,n] + bias[o]
// Block 64(o) x 128(n); ldmatrix fragments. (unchanged from R13)
// ---------------------------------------------------------------------------
template<int OUTC, int INC, bool CONCAT, bool BNRELU>
__global__ void __launch_bounds__(256)
gemm_mma(const float* __restrict__ W, const float* __restrict__ bias,
         const float* __restrict__ X0, const float* __restrict__ X1,
         float* __restrict__ Y,
         const float* __restrict__ gamma, const float* __restrict__ beta,
         const float* __restrict__ rmean, const float* __restrict__ rvar)
{
    __shared__ uint32_t AsH[64][GST],  AsL[64][GST];
    __shared__ uint32_t BsH[128][GST], BsL[128][GST];

    const int tid = threadIdx.x;
    const int n0 = blockIdx.x * 128;
    const int o0 = blockIdx.y * 64;
    const int b  = blockIdx.z;
    const int XC = CONCAT ? (INC / 2) : INC;
    const float* x0 = X0 + (size_t)b * XC * Nn;
    const float* x1 = CONCAT ? (X1 + (size_t)b * XC * Nn) : nullptr;

    const int w      = tid >> 5;
    const int lane   = tid & 31;
    const int g      = lane >> 2;
    const int tg     = lane & 3;
    const int warp_m = w >> 2;
    const int warp_n = w & 3;

    float acc[2][4][4] = {};

    const int o_ld  = tid >> 2;
    const int q4    = tid & 3;
    const int cp_ld = tid >> 4;
    const int nb_ld = tid & 15;

    const uint32_t aHb = cvta_smem(AsH), aLb = cvta_smem(AsL);
    const uint32_t bHb = cvta_smem(BsH), bLb = cvta_smem(BsL);
    const int la = (lane & 15) * GST + ((lane >> 4) << 2);
    const int lb = ((lane & 7) + ((lane >> 4) << 3)) * GST + (((lane >> 3) & 1) << 2);

    for (int c0 = 0; c0 < INC; c0 += 32) {
        {
            const float* wp = W + (size_t)(o0 + o_ld) * INC + c0 + q4 * 8;
            float4 u = *(const float4*)(wp);
            float4 v = *(const float4*)(wp + 4);
            uint4 hh, ll;
            pack_split(u.x, u.y, hh.x, ll.x);
            pack_split(u.z, u.w, hh.y, ll.y);
            pack_split(v.x, v.y, hh.z, ll.z);
            pack_split(v.z, v.w, hh.w, ll.w);
            *(uint4*)&AsH[o_ld][q4 * 4] = hh;
            *(uint4*)&AsL[o_ld][q4 * 4] = ll;
        }
        {
            int c = c0 + 2 * cp_ld;
            const float *xr0, *xr1;
            if (!CONCAT || c < INC / 2) {
                xr0 = x0 + (size_t)c * Nn;
                xr1 = x0 + (size_t)(c + 1) * Nn;
            } else {
                xr0 = x1 + (size_t)(c - INC / 2) * Nn;
                xr1 = x1 + (size_t)(c + 1 - INC / 2) * Nn;
            }
            #pragma unroll
            for (int i = 0; i < 8; i++) {
                int n = nb_ld + 16 * i;
                pack_split(xr0[n0 + n], xr1[n0 + n], BsH[n][cp_ld], BsL[n][cp_ld]);
            }
        }
        __syncthreads();

        #pragma unroll
        for (int st = 0; st < 2; st++) {
            const int kc = st * 8;
            uint32_t ah[2][4], al[2][4], bh[4][2], bl[4][2];
            #pragma unroll
            for (int mt = 0; mt < 2; mt++) {
                int idx = (warp_m * 32 + mt * 16) * GST + la + kc;
                ldsm_x4(ah[mt], aHb + idx * 4);
                ldsm_x4(al[mt], aLb + idx * 4);
            }
            #pragma unroll
            for (int pr = 0; pr < 2; pr++) {
                int idx = (warp_n * 32 + pr * 16) * GST + lb + kc;
                uint32_t th[4], tl[4];
                ldsm_x4(th, bHb + idx * 4);
                ldsm_x4(tl, bLb + idx * 4);
                bh[pr*2  ][0] = th[0]; bh[pr*2  ][1] = th[1];
                bh[pr*2+1][0] = th[2]; bh[pr*2+1][1] = th[3];
                bl[pr*2  ][0] = tl[0]; bl[pr*2  ][1] = tl[1];
                bl[pr*2+1][0] = tl[2]; bl[pr*2+1][1] = tl[3];
            }
            #pragma unroll
            for (int mt = 0; mt < 2; mt++)
                #pragma unroll
                for (int nt = 0; nt < 4; nt++)
                    mma3(acc[mt][nt], ah[mt], al[mt], bh[nt], bl[nt]);
        }
        __syncthreads();
    }

    float* yb = Y + (size_t)b * OUTC * Nn;
    #pragma unroll
    for (int mt = 0; mt < 2; mt++) {
        int r0 = o0 + warp_m * 32 + mt * 16 + g;
        int r1 = r0 + 8;
        float bv0 = bias[r0], bv1 = bias[r1];
        float sc0 = 1.f, sh0 = 0.f, sc1 = 1.f, sh1 = 0.f;
        if (BNRELU) {
            float rs0 = rsqrtf(rvar[r0] + 1e-3f);
            sc0 = gamma[r0] * rs0; sh0 = beta[r0] - rmean[r0] * sc0;
            float rs1 = rsqrtf(rvar[r1] + 1e-3f);
            sc1 = gamma[r1] * rs1; sh1 = beta[r1] - rmean[r1] * sc1;
        }
        #pragma unroll
        for (int nt = 0; nt < 4; nt++) {
            int n = n0 + warp_n * 32 + nt * 8 + 2 * tg;
            float t0 = acc[mt][nt][0] + bv0;
            float t1 = acc[mt][nt][1] + bv0;
            float t2 = acc[mt][nt][2] + bv1;
            float t3 = acc[mt][nt][3] + bv1;
            if (BNRELU) {
                t0 = fmaxf(t0 * sc0 + sh0, 0.f);
                t1 = fmaxf(t1 * sc0 + sh0, 0.f);
                t2 = fmaxf(t2 * sc1 + sh1, 0.f);
                t3 = fmaxf(t3 * sc1 + sh1, 0.f);
            }
            *(float2*)&yb[(size_t)r0 * Nn + n] = make_float2(t0, t1);
            *(float2*)&yb[(size_t)r1 * Nn + n] = make_float2(t2, t3);
        }
    }
}

// ---------------------------------------------------------------------------
// Scores + mask(bits) + exp: P_unnorm = mask ? exp(q·k/8) : 0, stored as
// interleaved uint2(hi,lo) bf16x2 per m-pair, plus partial row sums.
// Block 128(n) x 64(m). Warps 2(n) x 4(m); warp tile 64n x 16m.
// ---------------------------------------------------------------------------
__global__ void __launch_bounds__(256)
attn_scores_p()
{
    extern __shared__ uint32_t sm[];
    uint32_t* QH = sm;                                  // [128][AST]
    uint32_t* QL = sm + 128 * AST;
    uint32_t* KH = sm + 2 * 128 * AST;                  // [64][AST]
    uint32_t* KL = sm + 2 * 128 * AST + 64 * AST;
    float* RED   = (float*)(sm + 2 * 128 * AST + 2 * 64 * AST);  // [4][128]

    const int tid = threadIdx.x;
    const int m0 = blockIdx.x * 64;
    const int n0 = blockIdx.y * 128;
    const int bh = blockIdx.z;
    const int b = bh >> 2, h = bh & 3;
    const float* qg = g_q + (size_t)b * Dd * Nn;
    const float* kg = g_k + (size_t)b * Dd * Mm;

    const int w      = tid >> 5;
    const int lane   = tid & 31;
    const int g      = lane >> 2;
    const int tg     = lane & 3;
    const int warp_m = w >> 2;   // n half
    const int warp_n = w & 3;    // m quarter (16 m)

    float acc[4][2][4] = {};

    const int dpg = tid >> 4;   // 0..15
    const int cbl = tid & 15;

    #pragma unroll
    for (int hf = 0; hf < 2; hf++) {
        int dp  = dpg + 16 * hf;           // d-pair 0..31
        int ch0 = (2 * dp) * Hh + h;
        const float* q0 = qg + (size_t)ch0 * Nn + n0;
        const float* q1 = qg + (size_t)(ch0 + Hh) * Nn + n0;
        const float* k0 = kg + (size_t)ch0 * Mm + m0;
        const float* k1 = kg + (size_t)(ch0 + Hh) * Mm + m0;
        #pragma unroll
        for (int i = 0; i < 8; i++) {
            int n = cbl + 16 * i;
            pack_split(q0[n], q1[n], QH[n * AST + dp], QL[n * AST + dp]);
        }
        #pragma unroll
        for (int i = 0; i < 4; i++) {
            int m = cbl + 16 * i;
            pack_split(k0[m], k1[m], KH[m * AST + dp], KL[m * AST + dp]);
        }
    }
    __syncthreads();

    const uint32_t qHb = cvta_smem(QH), qLb = cvta_smem(QL);
    const uint32_t kHb = cvta_smem(KH), kLb = cvta_smem(KL);
    const int la = (lane & 15) * AST + ((lane >> 4) << 2);
    const int lb = ((lane & 7) + ((lane >> 4) << 3)) * AST + (((lane >> 3) & 1) << 2);

    #pragma unroll
    for (int st = 0; st < 4; st++) {
        const int kc = st * 8;
        uint32_t ah[4][4], al[4][4], bh2[2][2], bl2[2][2];
        #pragma unroll
        for (int mt = 0; mt < 4; mt++) {
            int idx = (warp_m * 64 + mt * 16) * AST + la + kc;
            ldsm_x4(ah[mt], qHb + idx * 4);
            ldsm_x4(al[mt], qLb + idx * 4);
        }
        {
            int idx = (warp_n * 16) * AST + lb + kc;
            uint32_t th[4], tl[4];
            ldsm_x4(th, kHb + idx * 4);
            ldsm_x4(tl, kLb + idx * 4);
            bh2[0][0] = th[0]; bh2[0][1] = th[1];
            bh2[1][0] = th[2]; bh2[1][1] = th[3];
            bl2[0][0] = tl[0]; bl2[0][1] = tl[1];
            bl2[1][0] = tl[2]; bl2[1][1] = tl[3];
        }
        #pragma unroll
        for (int mt = 0; mt < 4; mt++)
            #pragma unroll
            for (int nt = 0; nt < 2; nt++)
                mma3(acc[mt][nt], ah[mt], al[mt], bh2[nt], bl2[nt]);
    }

    // --- epilogue: mask bits, exp, uint2 P store, partial row sums ---
    float rsum[4][2];
    #pragma unroll
    for (int mt = 0; mt < 4; mt++) { rsum[mt][0] = 0.f; rsum[mt][1] = 0.f; }

    const int wordoff = (m0 + warp_n * 16) >> 5;   // one word covers this warp's 16 m
    const int bitbase = (warp_n * 16) & 31;

    #pragma unroll
    for (int mt = 0; mt < 4; mt++) {
        int nr0 = n0 + warp_m * 64 + mt * 16 + g;
        int nr1 = nr0 + 8;
        uint32_t w0 = g_maskbits[((size_t)b * Nn + nr0) * (Mm / 32) + wordoff];
        uint32_t w1 = g_maskbits[((size_t)b * Nn + nr1) * (Mm / 32) + wordoff];
        #pragma unroll
        for (int nt = 0; nt < 2; nt++) {
            int gm  = m0 + warp_n * 16 + nt * 8 + 2 * tg;
            int bit = bitbase + nt * 8 + 2 * tg;
            float p0 = ((w0 >> bit) & 1u)       ? __expf(acc[mt][nt][0] * 0.125f) : 0.f;
            float p1 = ((w0 >> (bit + 1)) & 1u) ? __expf(acc[mt][nt][1] * 0.125f) : 0.f;
            float p2 = ((w1 >> bit) & 1u)       ? __expf(acc[mt][nt][2] * 0.125f) : 0.f;
            float p3 = ((w1 >> (bit + 1)) & 1u) ? __expf(acc[mt][nt][3] * 0.125f) : 0.f;
            uint32_t hh, ll;
            pack_split(p0, p1, hh, ll);
            g_p[((size_t)bh * Nn + nr0) * (Mm / 2) + (gm >> 1)] = make_uint2(hh, ll);
            pack_split(p2, p3, hh, ll);
            g_p[((size_t)bh * Nn + nr1) * (Mm / 2) + (gm >> 1)] = make_uint2(hh, ll);
            rsum[mt][0] += p0 + p1;
            rsum[mt][1] += p2 + p3;
        }
    }
    #pragma unroll
    for (int mt = 0; mt < 4; mt++)
        #pragma unroll
        for (int r = 0; r < 2; r++) {
            rsum[mt][r] += __shfl_xor_sync(0xffffffffu, rsum[mt][r], 1);
            rsum[mt][r] += __shfl_xor_sync(0xffffffffu, rsum[mt][r], 2);
        }
    if (tg == 0) {
        #pragma unroll
        for (int mt = 0; mt < 4; mt++) {
            int rl = warp_m * 64 + mt * 16 + g;
            RED[warp_n * 128 + rl    ] = rsum[mt][0];
            RED[warp_n * 128 + rl + 8] = rsum[mt][1];
        }
    }
    __syncthreads();
    if (tid < 128) {
        float s = RED[tid] + RED[128 + tid] + RED[256 + tid] + RED[384 + tid];
        g_psum[((size_t)bh * Nn + n0 + tid) * 32 + blockIdx.x] = s;
    }
}

// ---------------------------------------------------------------------------
// Row-sum reduce: g_rowsum[row] = sum of 32 partials. 32768 rows.
// ---------------------------------------------------------------------------
__global__ void __launch_bounds__(256)
rowsum_reduce()
{
    int row = blockIdx.x * 256 + threadIdx.x;
    const float4* p = (const float4*)(g_psum + (size_t)row * 32);
    float s = 0.f;
    #pragma unroll
    for (int i = 0; i < 8; i++) {
        float4 v = p[i];
        s += v.x + v.y + v.z + v.w;
    }
    g_rowsum[row] = s;
}

// ---------------------------------------------------------------------------
// PV (bf16 3-term): msg = (sum_m P_unnorm * v) / rowsum.
// Block 64(d) x 128(n); m in chunks of 32. P loaded interleaved, de-paired.
// ---------------------------------------------------------------------------
__global__ void __launch_bounds__(256)
attn_pv_mma()
{
    __shared__ uint32_t VHs[64][GST],  VLs[64][GST];
    __shared__ uint32_t PHs[128][GST], PLs[128][GST];

    const int tid = threadIdx.x;
    const int n0 = blockIdx.x * 128;
    const int bh = blockIdx.z;
    const int b = bh >> 2, h = bh & 3;
    const float* vg = g_v + (size_t)b * Dd * Mm;
    const uint2* Pg = g_p + (size_t)bh * Nn * (Mm / 2);

    const int w      = tid >> 5;
    const int lane   = tid & 31;
    const int g      = lane >> 2;
    const int tg     = lane & 3;
    const int warp_m = w >> 2;
    const int warp_n = w & 3;

    float acc[2][4][4] = {};

    const int vd = tid >> 2;
    const int vq = tid & 3;
    const int pn = tid >> 1;
    const int ph = tid & 1;

    const uint32_t vHb = cvta_smem(VHs), vLb = cvta_smem(VLs);
    const uint32_t pHb = cvta_smem(PHs), pLb = cvta_smem(PLs);
    const int la = (lane & 15) * GST + ((lane >> 4) << 2);
    const int lb = ((lane & 7) + ((lane >> 4) << 3)) * GST + (((lane >> 3) & 1) << 2);

    for (int m0 = 0; m0 < Mm; m0 += 32) {
        // V tile
        {
            const float* vp = vg + (size_t)(vd * Hh + h) * Mm + m0 + vq * 8;
            float4 u = *(const float4*)(vp);
            float4 v4 = *(const float4*)(vp + 4);
            uint4 hh, ll;
            pack_split(u.x,  u.y,  hh.x, ll.x);
            pack_split(u.z,  u.w,  hh.y, ll.y);
            pack_split(v4.x, v4.y, hh.z, ll.z);
            pack_split(v4.z, v4.w, hh.w, ll.w);
            *(uint4*)&VHs[vd][vq * 4] = hh;
            *(uint4*)&VLs[vd][vq * 4] = ll;
        }
        // P tile: interleaved uint2 loads, de-interleave into planes
        {
            const uint2* pp = Pg + (size_t)(n0 + pn) * (Mm / 2) + (m0 >> 1) + ph * 8;
            uint4 a  = *(const uint4*)(pp);
            uint4 b4 = *(const uint4*)(pp + 2);
            uint4 c4 = *(const uint4*)(pp + 4);
            uint4 d4 = *(const uint4*)(pp + 6);
            *(uint4*)&PHs[pn][ph * 8    ] = make_uint4(a.x,  a.z,  b4.x, b4.z);
            *(uint4*)&PLs[pn][ph * 8    ] = make_uint4(a.y,  a.w,  b4.y, b4.w);
            *(uint4*)&PHs[pn][ph * 8 + 4] = make_uint4(c4.x, c4.z, d4.x, d4.z);
            *(uint4*)&PLs[pn][ph * 8 + 4] = make_uint4(c4.y, c4.w, d4.y, d4.w);
        }
        __syncthreads();

        #pragma unroll
        for (int st = 0; st < 2; st++) {
            const int kc = st * 8;
            uint32_t ah[2][4], al[2][4], bh2[4][2], bl2[4][2];
            #pragma unroll
            for (int mt = 0; mt < 2; mt++) {
                int idx = (warp_m * 32 + mt * 16) * GST + la + kc;
                ldsm_x4(ah[mt], vHb + idx * 4);
                ldsm_x4(al[mt], vLb + idx * 4);
            }
            #pragma unroll
            for (int pr = 0; pr < 2; pr++) {
                int idx = (warp_n * 32 + pr * 16) * GST + lb + kc;
                uint32_t th[4], tl[4];
                ldsm_x4(th, pHb + idx * 4);
                ldsm_x4(tl, pLb + idx * 4);
                bh2[pr*2  ][0] = th[0]; bh2[pr*2  ][1] = th[1];
                bh2[pr*2+1][0] = th[2]; bh2[pr*2+1][1] = th[3];
                bl2[pr*2  ][0] = tl[0]; bl2[pr*2  ][1] = tl[1];
                bl2[pr*2+1][0] = tl[2]; bl2[pr*2+1][1] = tl[3];
            }
            #pragma unroll
            for (int mt = 0; mt < 2; mt++)
                #pragma unroll
                for (int nt = 0; nt < 4; nt++)
                    mma3(acc[mt][nt], ah[mt], al[mt], bh2[nt], bl2[nt]);
        }
        __syncthreads();
    }

    const float* rs = g_rowsum + (size_t)bh * Nn + n0;
    float* mp = g_msg + (size_t)b * Dd * Nn;
    #pragma unroll
    for (int mt = 0; mt < 2; mt++) {
        int d0 = warp_m * 32 + mt * 16 + g;
        int d1 = d0 + 8;
        #pragma unroll
        for (int nt = 0; nt < 4; nt++) {
            int n = warp_n * 32 + nt * 8 + 2 * tg;
            float inv0 = 1.f / rs[n];
            float inv1 = 1.f / rs[n + 1];
            *(float2*)&mp[(size_t)(d0 * Hh + h) * Nn + n0 + n] =
                make_float2(acc[mt][nt][0] * inv0, acc[mt][nt][1] * inv1);
            *(float2*)&mp[(size_t)(d1 * Hh + h) * Nn + n0 + n] =
                make_float2(acc[mt][nt][2] * inv0, acc[mt][nt][3] * inv1);
        }
    }
}

// ---------------------------------------------------------------------------
extern "C" void kernel_launch(void* const* d_in, const int* in_sizes, int n_in,
                              void* d_out, int out_size)
{
    const float* x      = (const float*)d_in[0];
    const float* source = (const float*)d_in[1];
    const float* mask   = (const float*)d_in[2];
    const float* Wq = (const float*)d_in[3];
    const float* bq = (const float*)d_in[4];
    const float* Wk = (const float*)d_in[5];
    const float* bk = (const float*)d_in[6];
    const float* Wv = (const float*)d_in[7];
    const float* bv = (const float*)d_in[8];
    const float* Wm = (const float*)d_in[9];
    const float* bm = (const float*)d_in[10];
    const float* W1 = (const float*)d_in[11];
    const float* b1 = (const float*)d_in[12];
    const float* gamma = (const float*)d_in[13];
    const float* beta  = (const float*)d_in[14];
    const float* rmean = (const float*)d_in[15];
    const float* rvar  = (const float*)d_in[16];
    const float* W2 = (const float*)d_in[17];
    const float* b2 = (const float*)d_in[18];
    float* out = (float*)d_out;

    float *qb, *kb, *vb, *msgb, *messageb, *hb;
    cudaGetSymbolAddress((void**)&qb, g_q);
    cudaGetSymbolAddress((void**)&kb, g_k);
    cudaGetSymbolAddress((void**)&vb, g_v);
    cudaGetSymbolAddress((void**)&msgb, g_msg);
    cudaGetSymbolAddress((void**)&messageb, g_message);
    cudaGetSymbolAddress((void**)&hb, g_h);

    const int SMEM_SCORES = (2 * 128 * AST + 2 * 64 * AST + 512) * 4;  // 57344 B
    cudaFuncSetAttribute(attn_scores_p,
                         cudaFuncAttributeMaxDynamicSharedMemorySize, SMEM_SCORES);

    // mask bit-pack (overlaps with projections in-order; independent data)
    mask_pack<<<Bn * Nn * Mm / 256, 256>>>(mask);

    // q, k, v projections
    gemm_mma<256, 256, false, false><<<dim3(16, 4, 4), 256>>>(
        Wq, bq, x, nullptr, qb, nullptr, nullptr, nullptr, nullptr);
    gemm_mma<256, 256, false, false><<<dim3(16, 4, 4), 256>>>(
        Wk, bk, source, nullptr, kb, nullptr, nullptr, nullptr, nullptr);
    gemm_mma<256, 256, false, false><<<dim3(16, 4, 4), 256>>>(
        Wv, bv, source, nullptr, vb, nullptr, nullptr, nullptr, nullptr);

    // attention: P_unnorm + partial sums, reduce, PV with normalization
    attn_scores_p<<<dim3(32, 16, 16), 256, SMEM_SCORES>>>();
    rowsum_reduce<<<128, 256>>>();
    attn_pv_mma<<<dim3(16, 1, 16), 256>>>();

    // message projection
    gemm_mma<256, 256, false, false><<<dim3(16, 4, 4), 256>>>(
        Wm, bm, msgb, nullptr, messageb, nullptr, nullptr, nullptr, nullptr);

    // MLP layer 1 (concat[x, message]) + BN + ReLU
    gemm_mma<512, 512, true, true><<<dim3(16, 8, 4), 256>>>(
        W1, b1, x, messageb, hb, gamma, beta, rmean, rvar);

    // MLP layer 2 -> output
    gemm_mma<256, 512, false, false><<<dim3(16, 4, 4), 256>>>(
        W2, b2, hb, nullptr, out, nullptr, nullptr, nullptr, nullptr);
}

// round 15
// speedup vs baseline: 1.1429x; 1.1017x over previous
#include <cuda_runtime.h>
#include <cuda_fp16.h>
#include <math.h>
#include <float.h>
#include <stdint.h>

// Problem constants
#define Bn   4
#define Dd   256
#define Nn   2048
#define Mm   2048
#define Hh   4
#define DIMh 64

// Scratch (allocation-free: __device__ globals)
__device__ float g_q[Bn * Dd * Nn];
__device__ float g_k[Bn * Dd * Mm];
__device__ float g_v[Bn * Dd * Mm];
__device__ float g_msg[Bn * Dd * Nn];
__device__ float g_message[Bn * Dd * Nn];
__device__ float g_h[Bn * 2 * Dd * Nn];
// P_unnorm: f16x2 per m-pair (single plane)
__device__ uint32_t g_pf[(size_t)Bn * Hh * Nn * Mm / 2];   // 134 MB
__device__ float g_psum[(size_t)Bn * Hh * Nn * 32];
__device__ float g_rowsum[Bn * Hh * Nn];
__device__ uint32_t g_maskbits[Bn * Nn * Mm / 32];         // 2 MB

// ---------------------------------------------------------------------------
// split/pack helpers
// ---------------------------------------------------------------------------
__device__ __forceinline__ void pack_split(float f0, float f1, uint32_t& h, uint32_t& l)
{
    uint32_t hp;
    asm("cvt.rn.bf16x2.f32 %0, %1, %2;" : "=r"(hp) : "f"(f1), "f"(f0));
    float r0 = f0 - __uint_as_float(hp << 16);
    float r1 = f1 - __uint_as_float(hp & 0xffff0000u);
    uint32_t lp;
    asm("cvt.rn.bf16x2.f32 %0, %1, %2;" : "=r"(lp) : "f"(r1), "f"(r0));
    h = hp; l = lp;
}

__device__ __forceinline__ void pack_f16x2(float f0, float f1, uint32_t& r)
{
    asm("cvt.rn.f16x2.f32 %0, %1, %2;" : "=r"(r) : "f"(f1), "f"(f0));
}

// f16 2-level split: x = hi + lo, both f16 (captures ~22 mantissa bits)
__device__ __forceinline__ void split_f16(float f0, float f1, uint32_t& h, uint32_t& l)
{
    pack_f16x2(f0, f1, h);
    __half2 hv = *reinterpret_cast<__half2*>(&h);
    float2 hf = __half22float2(hv);
    pack_f16x2(f0 - hf.x, f1 - hf.y, l);
}

__device__ __forceinline__ void mma_bf16(float (&d)[4],
                                         uint32_t a0, uint32_t a1, uint32_t a2, uint32_t a3,
                                         uint32_t b0, uint32_t b1)
{
    asm volatile(
        "mma.sync.aligned.m16n8k16.row.col.f32.bf16.bf16.f32 "
        "{%0,%1,%2,%3}, {%4,%5,%6,%7}, {%8,%9}, {%0,%1,%2,%3};\n"
        : "+f"(d[0]), "+f"(d[1]), "+f"(d[2]), "+f"(d[3])
        : "r"(a0), "r"(a1), "r"(a2), "r"(a3), "r"(b0), "r"(b1));
}

__device__ __forceinline__ void mma_f16(float (&d)[4],
                                        uint32_t a0, uint32_t a1, uint32_t a2, uint32_t a3,
                                        uint32_t b0, uint32_t b1)
{
    asm volatile(
        "mma.sync.aligned.m16n8k16.row.col.f32.f16.f16.f32 "
        "{%0,%1,%2,%3}, {%4,%5,%6,%7}, {%8,%9}, {%0,%1,%2,%3};\n"
        : "+f"(d[0]), "+f"(d[1]), "+f"(d[2]), "+f"(d[3])
        : "r"(a0), "r"(a1), "r"(a2), "r"(a3), "r"(b0), "r"(b1));
}

__device__ __forceinline__ void mma3(float (&d)[4],
                                     const uint32_t (&ah)[4], const uint32_t (&al)[4],
                                     const uint32_t (&bh)[2], const uint32_t (&bl)[2])
{
    mma_bf16(d, al[0], al[1], al[2], al[3], bh[0], bh[1]);
    mma_bf16(d, ah[0], ah[1], ah[2], ah[3], bl[0], bl[1]);
    mma_bf16(d, ah[0], ah[1], ah[2], ah[3], bh[0], bh[1]);
}

// PV 2-term: acc += (Vh + Vl) * P   (f16 operands, fp32 accum)
__device__ __forceinline__ void mma2(float (&d)[4],
                                     const uint32_t (&ah)[4], const uint32_t (&al)[4],
                                     const uint32_t (&b)[2])
{
    mma_f16(d, al[0], al[1], al[2], al[3], b[0], b[1]);
    mma_f16(d, ah[0], ah[1], ah[2], ah[3], b[0], b[1]);
}

__device__ __forceinline__ void ldsm_x4(uint32_t (&r)[4], uint32_t saddr)
{
    asm volatile("ldmatrix.sync.aligned.m8n8.x4.shared.b16 {%0,%1,%2,%3}, [%4];"
                 : "=r"(r[0]), "=r"(r[1]), "=r"(r[2]), "=r"(r[3]) : "r"(saddr));
}

__device__ __forceinline__ uint32_t cvta_smem(const void* p)
{
    return (uint32_t)__cvta_generic_to_shared(p);
}

#define GST 20
#define AST 36

// ---------------------------------------------------------------------------
// Mask bit-pack
// ---------------------------------------------------------------------------
__global__ void __launch_bounds__(256)
mask_pack(const float* __restrict__ mask)
{
    int idx = blockIdx.x * 256 + threadIdx.x;
    float v = mask[idx];
    unsigned bits = __ballot_sync(0xffffffffu, v > 0.f);
    if ((threadIdx.x & 31) == 0)
        g_maskbits[idx >> 5] = bits;
}

// ---------------------------------------------------------------------------
// Shared GEMM body (bf16 3-term, ldmatrix). Block 64(o) x 128(n).
// ---------------------------------------------------------------------------
template<int OUTC, int INC, bool CONCAT, bool BNRELU>
__device__ __forceinline__ void gemm_body(
    int n0, int o0, int b,
    const float* __restrict__ W, const float* __restrict__ bias,
    const float* __restrict__ X0, const float* __restrict__ X1,
    float* __restrict__ Y,
    const float* __restrict__ gamma, const float* __restrict__ beta,
    const float* __restrict__ rmean, const float* __restrict__ rvar)
{
    __shared__ uint32_t AsH[64][GST],  AsL[64][GST];
    __shared__ uint32_t BsH[128][GST], BsL[128][GST];

    const int tid = threadIdx.x;
    const int XC = CONCAT ? (INC / 2) : INC;
    const float* x0 = X0 + (size_t)b * XC * Nn;
    const float* x1 = CONCAT ? (X1 + (size_t)b * XC * Nn) : nullptr;

    const int w      = tid >> 5;
    const int lane   = tid & 31;
    const int g      = lane >> 2;
    const int tg     = lane & 3;
    const int warp_m = w >> 2;
    const int warp_n = w & 3;

    float acc[2][4][4] = {};

    const int o_ld  = tid >> 2;
    const int q4    = tid & 3;
    const int cp_ld = tid >> 4;
    const int nb_ld = tid & 15;

    const uint32_t aHb = cvta_smem(AsH), aLb = cvta_smem(AsL);
    const uint32_t bHb = cvta_smem(BsH), bLb = cvta_smem(BsL);
    const int la = (lane & 15) * GST + ((lane >> 4) << 2);
    const int lb = ((lane & 7) + ((lane >> 4) << 3)) * GST + (((lane >> 3) & 1) << 2);

    for (int c0 = 0; c0 < INC; c0 += 32) {
        {
            const float* wp = W + (size_t)(o0 + o_ld) * INC + c0 + q4 * 8;
            float4 u = *(const float4*)(wp);
            float4 v = *(const float4*)(wp + 4);
            uint4 hh, ll;
            pack_split(u.x, u.y, hh.x, ll.x);
            pack_split(u.z, u.w, hh.y, ll.y);
            pack_split(v.x, v.y, hh.z, ll.z);
            pack_split(v.z, v.w, hh.w, ll.w);
            *(uint4*)&AsH[o_ld][q4 * 4] = hh;
            *(uint4*)&AsL[o_ld][q4 * 4] = ll;
        }
        {
            int c = c0 + 2 * cp_ld;
            const float *xr0, *xr1;
            if (!CONCAT || c < INC / 2) {
                xr0 = x0 + (size_t)c * Nn;
                xr1 = x0 + (size_t)(c + 1) * Nn;
            } else {
                xr0 = x1 + (size_t)(c - INC / 2) * Nn;
                xr1 = x1 + (size_t)(c + 1 - INC / 2) * Nn;
            }
            #pragma unroll
            for (int i = 0; i < 8; i++) {
                int n = nb_ld + 16 * i;
                pack_split(xr0[n0 + n], xr1[n0 + n], BsH[n][cp_ld], BsL[n][cp_ld]);
            }
        }
        __syncthreads();

        #pragma unroll
        for (int st = 0; st < 2; st++) {
            const int kc = st * 8;
            uint32_t ah[2][4], al[2][4], bh[4][2], bl[4][2];
            #pragma unroll
            for (int mt = 0; mt < 2; mt++) {
                int idx = (warp_m * 32 + mt * 16) * GST + la + kc;
                ldsm_x4(ah[mt], aHb + idx * 4);
                ldsm_x4(al[mt], aLb + idx * 4);
            }
            #pragma unroll
            for (int pr = 0; pr < 2; pr++) {
                int idx = (warp_n * 32 + pr * 16) * GST + lb + kc;
                uint32_t th[4], tl[4];
                ldsm_x4(th, bHb + idx * 4);
                ldsm_x4(tl, bLb + idx * 4);
                bh[pr*2  ][0] = th[0]; bh[pr*2  ][1] = th[1];
                bh[pr*2+1][0] = th[2]; bh[pr*2+1][1] = th[3];
                bl[pr*2  ][0] = tl[0]; bl[pr*2  ][1] = tl[1];
                bl[pr*2+1][0] = tl[2]; bl[pr*2+1][1] = tl[3];
            }
            #pragma unroll
            for (int mt = 0; mt < 2; mt++)
                #pragma unroll
                for (int nt = 0; nt < 4; nt++)
                    mma3(acc[mt][nt], ah[mt], al[mt], bh[nt], bl[nt]);
        }
        __syncthreads();
    }

    float* yb = Y + (size_t)b * OUTC * Nn;
    #pragma unroll
    for (int mt = 0; mt < 2; mt++) {
        int r0 = o0 + warp_m * 32 + mt * 16 + g;
        int r1 = r0 + 8;
        float bv0 = bias[r0], bv1 = bias[r1];
        float sc0 = 1.f, sh0 = 0.f, sc1 = 1.f, sh1 = 0.f;
        if (BNRELU) {
            float rs0 = rsqrtf(rvar[r0] + 1e-3f);
            sc0 = gamma[r0] * rs0; sh0 = beta[r0] - rmean[r0] * sc0;
            float rs1 = rsqrtf(rvar[r1] + 1e-3f);
            sc1 = gamma[r1] * rs1; sh1 = beta[r1] - rmean[r1] * sc1;
        }
        #pragma unroll
        for (int nt = 0; nt < 4; nt++) {
            int n = n0 + warp_n * 32 + nt * 8 + 2 * tg;
            float t0 = acc[mt][nt][0] + bv0;
            float t1 = acc[mt][nt][1] + bv0;
            float t2 = acc[mt][nt][2] + bv1;
            float t3 = acc[mt][nt][3] + bv1;
            if (BNRELU) {
                t0 = fmaxf(t0 * sc0 + sh0, 0.f);
                t1 = fmaxf(t1 * sc0 + sh0, 0.f);
                t2 = fmaxf(t2 * sc1 + sh1, 0.f);
                t3 = fmaxf(t3 * sc1 + sh1, 0.f);
            }
            *(float2*)&yb[(size_t)r0 * Nn + n] = make_float2(t0, t1);
            *(float2*)&yb[(size_t)r1 * Nn + n] = make_float2(t2, t3);
        }
    }
}

template<int OUTC, int INC, bool CONCAT, bool BNRELU>
__global__ void __launch_bounds__(256)
gemm_mma(const float* __restrict__ W, const float* __restrict__ bias,
         const float* __restrict__ X0, const float* __restrict__ X1,
         float* __restrict__ Y,
         const float* __restrict__ gamma, const float* __restrict__ beta,
         const float* __restrict__ rmean, const float* __restrict__ rvar)
{
    gemm_body<OUTC, INC, CONCAT, BNRELU>(
        blockIdx.x * 128, blockIdx.y * 64, blockIdx.z,
        W, bias, X0, X1, Y, gamma, beta, rmean, rvar);
}

// Fused q/k/v projections: blockIdx.z = op*4 + batch (one launch, 768 blocks)
__global__ void __launch_bounds__(256)
qkv_mma(const float* __restrict__ Wq, const float* __restrict__ bq,
        const float* __restrict__ Wk, const float* __restrict__ bk,
        const float* __restrict__ Wv, const float* __restrict__ bv,
        const float* __restrict__ x, const float* __restrict__ source,
        float* __restrict__ q, float* __restrict__ k, float* __restrict__ v)
{
    const int op = blockIdx.z >> 2;
    const int b  = blockIdx.z & 3;
    const float* W    = (op == 0) ? Wq : (op == 1) ? Wk : Wv;
    const float* bias = (op == 0) ? bq : (op == 1) ? bk : bv;
    const float* X    = (op == 0) ? x : source;
    float* Y          = (op == 0) ? q : (op == 1) ? k : v;
    gemm_body<256, 256, false, false>(
        blockIdx.x * 128, blockIdx.y * 64, b,
        W, bias, X, nullptr, Y, nullptr, nullptr, nullptr, nullptr);
}

// ---------------------------------------------------------------------------
// Scores + mask(bits) + exp: P_unnorm = mask ? exp(q·k/8) : 0, stored as
// f16x2 per m-pair (single plane), plus partial row sums.
// Block 128(n) x 64(m). QK^T stays bf16 3-term.
// ---------------------------------------------------------------------------
__global__ void __launch_bounds__(256)
attn_scores_p()
{
    extern __shared__ uint32_t sm[];
    uint32_t* QH = sm;                                  // [128][AST]
    uint32_t* QL = sm + 128 * AST;
    uint32_t* KH = sm + 2 * 128 * AST;                  // [64][AST]
    uint32_t* KL = sm + 2 * 128 * AST + 64 * AST;
    float* RED   = (float*)(sm + 2 * 128 * AST + 2 * 64 * AST);

    const int tid = threadIdx.x;
    const int m0 = blockIdx.x * 64;
    const int n0 = blockIdx.y * 128;
    const int bh = blockIdx.z;
    const int b = bh >> 2, h = bh & 3;
    const float* qg = g_q + (size_t)b * Dd * Nn;
    const float* kg = g_k + (size_t)b * Dd * Mm;

    const int w      = tid >> 5;
    const int lane   = tid & 31;
    const int g      = lane >> 2;
    const int tg     = lane & 3;
    const int warp_m = w >> 2;
    const int warp_n = w & 3;

    float acc[4][2][4] = {};

    const int dpg = tid >> 4;
    const int cbl = tid & 15;

    #pragma unroll
    for (int hf = 0; hf < 2; hf++) {
        int dp  = dpg + 16 * hf;
        int ch0 = (2 * dp) * Hh + h;
        const float* q0 = qg + (size_t)ch0 * Nn + n0;
        const float* q1 = qg + (size_t)(ch0 + Hh) * Nn + n0;
        const float* k0 = kg + (size_t)ch0 * Mm + m0;
        const float* k1 = kg + (size_t)(ch0 + Hh) * Mm + m0;
        #pragma unroll
        for (int i = 0; i < 8; i++) {
            int n = cbl + 16 * i;
            pack_split(q0[n], q1[n], QH[n * AST + dp], QL[n * AST + dp]);
        }
        #pragma unroll
        for (int i = 0; i < 4; i++) {
            int m = cbl + 16 * i;
            pack_split(k0[m], k1[m], KH[m * AST + dp], KL[m * AST + dp]);
        }
    }
    __syncthreads();

    const uint32_t qHb = cvta_smem(QH), qLb = cvta_smem(QL);
    const uint32_t kHb = cvta_smem(KH), kLb = cvta_smem(KL);
    const int la = (lane & 15) * AST + ((lane >> 4) << 2);
    const int lb = ((lane & 7) + ((lane >> 4) << 3)) * AST + (((lane >> 3) & 1) << 2);

    #pragma unroll
    for (int st = 0; st < 4; st++) {
        const int kc = st * 8;
        uint32_t ah[4][4], al[4][4], bh2[2][2], bl2[2][2];
        #pragma unroll
        for (int mt = 0; mt < 4; mt++) {
            int idx = (warp_m * 64 + mt * 16) * AST + la + kc;
            ldsm_x4(ah[mt], qHb + idx * 4);
            ldsm_x4(al[mt], qLb + idx * 4);
        }
        {
            int idx = (warp_n * 16) * AST + lb + kc;
            uint32_t th[4], tl[4];
            ldsm_x4(th, kHb + idx * 4);
            ldsm_x4(tl, kLb + idx * 4);
            bh2[0][0] = th[0]; bh2[0][1] = th[1];
            bh2[1][0] = th[2]; bh2[1][1] = th[3];
            bl2[0][0] = tl[0]; bl2[0][1] = tl[1];
            bl2[1][0] = tl[2]; bl2[1][1] = tl[3];
        }
        #pragma unroll
        for (int mt = 0; mt < 4; mt++)
            #pragma unroll
            for (int nt = 0; nt < 2; nt++)
                mma3(acc[mt][nt], ah[mt], al[mt], bh2[nt], bl2[nt]);
    }

    // --- epilogue: mask bits, exp, f16x2 P store, partial row sums ---
    float rsum[4][2];
    #pragma unroll
    for (int mt = 0; mt < 4; mt++) { rsum[mt][0] = 0.f; rsum[mt][1] = 0.f; }

    const int wordoff = (m0 + warp_n * 16) >> 5;
    const int bitbase = (warp_n * 16) & 31;

    #pragma unroll
    for (int mt = 0; mt < 4; mt++) {
        int nr0 = n0 + warp_m * 64 + mt * 16 + g;
        int nr1 = nr0 + 8;
        uint32_t w0 = g_maskbits[((size_t)b * Nn + nr0) * (Mm / 32) + wordoff];
        uint32_t w1 = g_maskbits[((size_t)b * Nn + nr1) * (Mm / 32) + wordoff];
        #pragma unroll
        for (int nt = 0; nt < 2; nt++) {
            int gm  = m0 + warp_n * 16 + nt * 8 + 2 * tg;
            int bit = bitbase + nt * 8 + 2 * tg;
            float p0 = ((w0 >> bit) & 1u)       ? __expf(acc[mt][nt][0] * 0.125f) : 0.f;
            float p1 = ((w0 >> (bit + 1)) & 1u) ? __expf(acc[mt][nt][1] * 0.125f) : 0.f;
            float p2 = ((w1 >> bit) & 1u)       ? __expf(acc[mt][nt][2] * 0.125f) : 0.f;
            float p3 = ((w1 >> (bit + 1)) & 1u) ? __expf(acc[mt][nt][3] * 0.125f) : 0.f;
            uint32_t u;
            pack_f16x2(p0, p1, u);
            g_pf[((size_t)bh * Nn + nr0) * (Mm / 2) + (gm >> 1)] = u;
            pack_f16x2(p2, p3, u);
            g_pf[((size_t)bh * Nn + nr1) * (Mm / 2) + (gm >> 1)] = u;
            rsum[mt][0] += p0 + p1;
            rsum[mt][1] += p2 + p3;
        }
    }
    #pragma unroll
    for (int mt = 0; mt < 4; mt++)
        #pragma unroll
        for (int r = 0; r < 2; r++) {
            rsum[mt][r] += __shfl_xor_sync(0xffffffffu, rsum[mt][r], 1);
            rsum[mt][r] += __shfl_xor_sync(0xffffffffu, rsum[mt][r], 2);
        }
    if (tg == 0) {
        #pragma unroll
        for (int mt = 0; mt < 4; mt++) {
            int rl = warp_m * 64 + mt * 16 + g;
            RED[warp_n * 128 + rl    ] = rsum[mt][0];
            RED[warp_n * 128 + rl + 8] = rsum[mt][1];
        }
    }
    __syncthreads();
    if (tid < 128) {
        float s = RED[tid] + RED[128 + tid] + RED[256 + tid] + RED[384 + tid];
        g_psum[((size_t)bh * Nn + n0 + tid) * 32 + blockIdx.x] = s;
    }
}

// ---------------------------------------------------------------------------
// Row-sum reduce
// ---------------------------------------------------------------------------
__global__ void __launch_bounds__(256)
rowsum_reduce()
{
    int row = blockIdx.x * 256 + threadIdx.x;
    const float4* p = (const float4*)(g_psum + (size_t)row * 32);
    float s = 0.f;
    #pragma unroll
    for (int i = 0; i < 8; i++) {
        float4 v = p[i];
        s += v.x + v.y + v.z + v.w;
    }
    g_rowsum[row] = s;
}

// ---------------------------------------------------------------------------
// PV (f16, 2-term): msg = (sum_m P_f16 * (V_hi + V_lo)) / rowsum.
// Block 64(d) x 128(n); m in chunks of 32. P single plane.
// ---------------------------------------------------------------------------
__global__ void __launch_bounds__(256)
attn_pv_mma()
{
    __shared__ uint32_t VHs[64][GST], VLs[64][GST];   // [d][m-pair] f16 planes
    __shared__ uint32_t Ps[128][GST];                 // [n][m-pair] f16 plane

    const int tid = threadIdx.x;
    const int n0 = blockIdx.x * 128;
    const int bh = blockIdx.z;
    const int b = bh >> 2, h = bh & 3;
    const float* vg = g_v + (size_t)b * Dd * Mm;
    const uint32_t* Pg = g_pf + (size_t)bh * Nn * (Mm / 2);

    const int w      = tid >> 5;
    const int lane   = tid & 31;
    const int g      = lane >> 2;
    const int tg     = lane & 3;
    const int warp_m = w >> 2;
    const int warp_n = w & 3;

    float acc[2][4][4] = {};

    const int vd = tid >> 2;
    const int vq = tid & 3;
    const int pn = tid >> 1;
    const int ph = tid & 1;

    const uint32_t vHb = cvta_smem(VHs), vLb = cvta_smem(VLs);
    const uint32_t pBb = cvta_smem(Ps);
    const int la = (lane & 15) * GST + ((lane >> 4) << 2);
    const int lb = ((lane & 7) + ((lane >> 4) << 3)) * GST + (((lane >> 3) & 1) << 2);

    for (int m0 = 0; m0 < Mm; m0 += 32) {
        // V tile (f16 hi/lo)
        {
            const float* vp = vg + (size_t)(vd * Hh + h) * Mm + m0 + vq * 8;
            float4 u = *(const float4*)(vp);
            float4 v4 = *(const float4*)(vp + 4);
            uint4 hh, ll;
            split_f16(u.x,  u.y,  hh.x, ll.x);
            split_f16(u.z,  u.w,  hh.y, ll.y);
            split_f16(v4.x, v4.y, hh.z, ll.z);
            split_f16(v4.z, v4.w, hh.w, ll.w);
            *(uint4*)&VHs[vd][vq * 4] = hh;
            *(uint4*)&VLs[vd][vq * 4] = ll;
        }
        // P tile: single plane, direct uint4 loads
        {
            const uint32_t* pp = Pg + (size_t)(n0 + pn) * (Mm / 2) + (m0 >> 1) + ph * 8;
            *(uint4*)&Ps[pn][ph * 8    ] = *(const uint4*)(pp);
            *(uint4*)&Ps[pn][ph * 8 + 4] = *(const uint4*)(pp + 4);
        }
        __syncthreads();

        #pragma unroll
        for (int st = 0; st < 2; st++) {
            const int kc = st * 8;
            uint32_t ah[2][4], al[2][4], bf[4][2];
            #pragma unroll
            for (int mt = 0; mt < 2; mt++) {
                int idx = (warp_m * 32 + mt * 16) * GST + la + kc;
                ldsm_x4(ah[mt], vHb + idx * 4);
                ldsm_x4(al[mt], vLb + idx * 4);
            }
            #pragma unroll
            for (int pr = 0; pr < 2; pr++) {
                int idx = (warp_n * 32 + pr * 16) * GST + lb + kc;
                uint32_t t[4];
                ldsm_x4(t, pBb + idx * 4);
                bf[pr*2  ][0] = t[0]; bf[pr*2  ][1] = t[1];
                bf[pr*2+1][0] = t[2]; bf[pr*2+1][1] = t[3];
            }
            #pragma unroll
            for (int mt = 0; mt < 2; mt++)
                #pragma unroll
                for (int nt = 0; nt < 4; nt++)
                    mma2(acc[mt][nt], ah[mt], al[mt], bf[nt]);
        }
        __syncthreads();
    }

    const float* rs = g_rowsum + (size_t)bh * Nn + n0;
    float* mp = g_msg + (size_t)b * Dd * Nn;
    #pragma unroll
    for (int mt = 0; mt < 2; mt++) {
        int d0 = warp_m * 32 + mt * 16 + g;
        int d1 = d0 + 8;
        #pragma unroll
        for (int nt = 0; nt < 4; nt++) {
            int n = warp_n * 32 + nt * 8 + 2 * tg;
            float inv0 = 1.f / rs[n];
            float inv1 = 1.f / rs[n + 1];
            *(float2*)&mp[(size_t)(d0 * Hh + h) * Nn + n0 + n] =
                make_float2(acc[mt][nt][0] * inv0, acc[mt][nt][1] * inv1);
            *(float2*)&mp[(size_t)(d1 * Hh + h) * Nn + n0 + n] =
                make_float2(acc[mt][nt][2] * inv0, acc[mt][nt][3] * inv1);
        }
    }
}

// ---------------------------------------------------------------------------
extern "C" void kernel_launch(void* const* d_in, const int* in_sizes, int n_in,
                              void* d_out, int out_size)
{
    const float* x      = (const float*)d_in[0];
    const float* source = (const float*)d_in[1];
    const float* mask   = (const float*)d_in[2];
    const float* Wq = (const float*)d_in[3];
    const float* bq = (const float*)d_in[4];
    const float* Wk = (const float*)d_in[5];
    const float* bk = (const float*)d_in[6];
    const float* Wv = (const float*)d_in[7];
    const float* bv = (const float*)d_in[8];
    const float* Wm = (const float*)d_in[9];
    const float* bm = (const float*)d_in[10];
    const float* W1 = (const float*)d_in[11];
    const float* b1 = (const float*)d_in[12];
    const float* gamma = (const float*)d_in[13];
    const float* beta  = (const float*)d_in[14];
    const float* rmean = (const float*)d_in[15];
    const float* rvar  = (const float*)d_in[16];
    const float* W2 = (const float*)d_in[17];
    const float* b2 = (const float*)d_in[18];
    float* out = (float*)d_out;

    float *qb, *kb, *vb, *msgb, *messageb, *hb;
    cudaGetSymbolAddress((void**)&qb, g_q);
    cudaGetSymbolAddress((void**)&kb, g_k);
    cudaGetSymbolAddress((void**)&vb, g_v);
    cudaGetSymbolAddress((void**)&msgb, g_msg);
    cudaGetSymbolAddress((void**)&messageb, g_message);
    cudaGetSymbolAddress((void**)&hb, g_h);

    const int SMEM_SCORES = (2 * 128 * AST + 2 * 64 * AST + 512) * 4;  // 57344 B
    cudaFuncSetAttribute(attn_scores_p,
                         cudaFuncAttributeMaxDynamicSharedMemorySize, SMEM_SCORES);

    // mask bit-pack
    mask_pack<<<Bn * Nn * Mm / 256, 256>>>(mask);

    // fused q/k/v projections (one launch, 768 blocks)
    qkv_mma<<<dim3(16, 4, 12), 256>>>(Wq, bq, Wk, bk, Wv, bv, x, source, qb, kb, vb);

    // attention: P_unnorm + partial sums, reduce, PV with normalization
    attn_scores_p<<<dim3(32, 16, 16), 256, SMEM_SCORES>>>();
    rowsum_reduce<<<128, 256>>>();
    attn_pv_mma<<<dim3(16, 1, 16), 256>>>();

    // message projection
    gemm_mma<256, 256, false, false><<<dim3(16, 4, 4), 256>>>(
        Wm, bm, msgb, nullptr, messageb, nullptr, nullptr, nullptr, nullptr);

    // MLP layer 1 (concat[x, message]) + BN + ReLU
    gemm_mma<512, 512, true, true><<<dim3(16, 8, 4), 256>>>(
        W1, b1, x, messageb, hb, gamma, beta, rmean, rvar);

    // MLP layer 2 -> output
    gemm_mma<256, 512, false, false><<<dim3(16, 4, 4), 256>>>(
        W2, b2, hb, nullptr, out, nullptr, nullptr, nullptr, nullptr);
}